// round 14
// baseline (speedup 1.0000x reference)
#include <cuda_runtime.h>
#include <cuda_fp16.h>
#include <math.h>
#include <stdint.h>

// ---------------- problem constants ----------------
#define BB    4
#define TT    1000000
#define EE    8
#define CC    128
#define TOUT  1953
#define MROWS (BB * TOUT)          // 7812
#define MP    7936                 // padded M = 62*128
#define NCOLS 512
#define KDIM  4096
#define GCHUNKS 63                 // 31-row chunks per batch (63*31 = 1953)

// ---------------- GEMM tiling ----------------
#define BM 128
#define BN 128
#define BKC 64                     // K elems per stage
#define NKC (KDIM / BKC)           // 64 chunks
#define STAGE_BYTES 32768          // A 16K + B 16K (fp16)
#define NSTAGE 3
#define SMEM_DYN (NSTAGE * STAGE_BYTES)   // 98304

// gct_q smem: 128 x 129 floats (padded) + 128 gs
#define GCTQ_SMEM ((128 * 129 + 128) * 4)

// ---------------- scratch ----------------
__device__ __half d_Ah[(size_t)MP * KDIM];
__device__ __half d_Bh[(size_t)NCOLS * KDIM];   // column-interleaved (a,gate pairs)
__device__ float d_U[(size_t)MP * 256];   // GLU out [row][ctx 0..127 | main 0..127]
__device__ float d_WsT[2][CC * CC];
__device__ float d_gpart[BB * GCHUNKS * CC];
__device__ float d_q[BB * CC];
__device__ float d_part[BB * GCHUNKS * CC];

// ---------------- PTX helpers ----------------
__device__ __forceinline__ uint32_t smem_u32(const void* p) {
    uint32_t a;
    asm("{ .reg .u64 t; cvta.to.shared.u64 t, %1; cvt.u32.u64 %0, t; }" : "=r"(a) : "l"(p));
    return a;
}
#define CP16(dst, src) asm volatile("cp.async.cg.shared.global [%0], [%1], 16;" :: "r"(dst), "l"(src) : "memory")
#define CP_COMMIT()    asm volatile("cp.async.commit_group;" ::: "memory")
#define CP_WAIT1()     asm volatile("cp.async.wait_group 1;" ::: "memory")

#define LDSM4(r0, r1, r2, r3, addr)                                         \
    asm volatile("ldmatrix.sync.aligned.m8n8.x4.shared.b16 {%0,%1,%2,%3}, [%4];" \
        : "=r"(r0), "=r"(r1), "=r"(r2), "=r"(r3) : "r"(addr))

#define MMA16816(d, a, b)                                                   \
    asm volatile("mma.sync.aligned.m16n8k16.row.col.f32.f16.f16.f32 "       \
        "{%0,%1,%2,%3}, {%4,%5,%6,%7}, {%8,%9}, {%0,%1,%2,%3};"             \
        : "+f"((d)[0]), "+f"((d)[1]), "+f"((d)[2]), "+f"((d)[3])            \
        : "r"((a)[0]), "r"((a)[1]), "r"((a)[2]), "r"((a)[3]),               \
          "r"((b)[0]), "r"((b)[1]))

// swizzled byte offset within a 128B-row tile: row r, 16B-column c16
__device__ __forceinline__ uint32_t tile_off(int r, int c16) {
    return (uint32_t)(r * 128 + ((c16 * 16) ^ ((r & 7) << 4)));
}

// ============================================================
// Prep: convert x windows to fp16 (rows padded to MP)
// ============================================================
__global__ void prep_fp16A(const float* __restrict__ x) {
    int r = blockIdx.y;
    int k = blockIdx.x * 2048 + threadIdx.x * 8;
    size_t o = (size_t)r * KDIM + k;
    if (r >= MROWS) {
        *(uint4*)(d_Ah + o) = make_uint4(0, 0, 0, 0);
        return;
    }
    int b = r / TOUT, t = r % TOUT;
    const float* src = x + (size_t)b * TT * EE + (size_t)t * KDIM + k;
    float4 v0 = *(const float4*)(src);
    float4 v1 = *(const float4*)(src + 4);
    __half2* ph = (__half2*)(d_Ah + o);
    ph[0] = __floats2half2_rn(v0.x, v0.y);
    ph[1] = __floats2half2_rn(v0.z, v0.w);
    ph[2] = __floats2half2_rn(v1.x, v1.y);
    ph[3] = __floats2half2_rn(v1.z, v1.w);
}

// B with column interleave: n_new = branch*256 + pair*2 + half
// (pair = GLU channel, half 0 = "a", 1 = "gate"); kk = k*8 + e
__global__ void prep_fp16B(const float* __restrict__ cw, const float* __restrict__ mw) {
    int idx = blockIdx.x * 256 + threadIdx.x;
    if (idx >= NCOLS * KDIM) return;
    int n = idx >> 12, kk = idx & 4095;
    int branch = n >> 8;
    int within = n & 255;
    int pair = within >> 1, half = within & 1;
    int oc = half * 128 + pair;               // original out-channel within branch
    int e = kk & 7, k = kk >> 3;
    const float* w = branch ? mw : cw;
    d_Bh[idx] = __float2half_rn(w[(size_t)oc * KDIM + e * 512 + k]);
}

__global__ void prep_wst(const float* __restrict__ cs, const float* __restrict__ ms) {
    int idx = blockIdx.x * 256 + threadIdx.x;
    if (idx >= CC * CC) return;
    int o = idx / CC, c = idx % CC;
    d_WsT[0][c * CC + o] = cs[o * CC + c];
    d_WsT[1][c * CC + o] = ms[o * CC + c];
}

// ============================================================
// K1: fp16 HMMA GEMM + fused bias/GLU -> d_U   (R10 verbatim)
//     grid (4, 62); 128 threads = 4 warps (2m x 2n),
//     warp tile 64x64, 3-stage cp.async, 2 CTAs/SM.
// ============================================================
__global__ __launch_bounds__(128, 2) void gemm_tc(const float* __restrict__ ccb,
                                                  const float* __restrict__ mcb) {
    extern __shared__ char smem[];
    uint32_t sbase = smem_u32(smem);
    int tid = threadIdx.x;
    int lane = tid & 31, wid = tid >> 5;
    int wm = wid & 1, wn = wid >> 1;          // 2 x 2 warp grid
    int bn = blockIdx.x, bm = blockIdx.y;
    int m0 = bm * BM, n0 = bn * BN;

    int l15 = lane & 15, hh = lane >> 4;
    uint32_t cA[4], swA[4], cB[4], swB[4];
#pragma unroll
    for (int mt = 0; mt < 4; mt++) {
        int r = wm * 64 + mt * 16 + l15;
        cA[mt] = (uint32_t)(r * 128);
        swA[mt] = (uint32_t)((r & 7) << 4);
    }
#pragma unroll
    for (int q = 0; q < 4; q++) {
        int r = wn * 64 + q * 16 + l15;
        cB[q] = (uint32_t)(r * 128);
        swB[q] = (uint32_t)((r & 7) << 4);
    }

    float acc[4][8][4];
#pragma unroll
    for (int mt = 0; mt < 4; mt++)
#pragma unroll
        for (int nt = 0; nt < 8; nt++)
#pragma unroll
            for (int i = 0; i < 4; i++) acc[mt][nt][i] = 0.f;

    // ---- prologue: load stages 0,1 (8 A + 8 B cp.async per thread) ----
#pragma unroll
    for (int s = 0; s < 2; s++) {
        uint32_t stg = sbase + s * STAGE_BYTES;
        size_t koff = (size_t)s * BKC;
#pragma unroll
        for (int i = 0; i < 8; i++) {
            int idx = tid + i * 128;
            int row = idx >> 3, c16 = idx & 7;
            uint32_t dst = tile_off(row, c16);
            size_t ga = (size_t)(m0 + row) * KDIM + koff + c16 * 8;
            size_t gb = (size_t)(n0 + row) * KDIM + koff + c16 * 8;
            CP16(stg + dst,         d_Ah + ga);
            CP16(stg + 16384 + dst, d_Bh + gb);
        }
        CP_COMMIT();
    }

    // ---- main loop ----
    for (int c = 0; c < NKC; c++) {
        CP_WAIT1();
        __syncthreads();

        if (c + 2 < NKC) {
            uint32_t stg = sbase + ((c + 2) % NSTAGE) * STAGE_BYTES;
            size_t koff = (size_t)(c + 2) * BKC;
#pragma unroll
            for (int i = 0; i < 8; i++) {
                int idx = tid + i * 128;
                int row = idx >> 3, c16 = idx & 7;
                uint32_t dst = tile_off(row, c16);
                size_t ga = (size_t)(m0 + row) * KDIM + koff + c16 * 8;
                size_t gb = (size_t)(n0 + row) * KDIM + koff + c16 * 8;
                CP16(stg + dst,         d_Ah + ga);
                CP16(stg + 16384 + dst, d_Bh + gb);
            }
        }
        CP_COMMIT();

        uint32_t stA = sbase + (c % NSTAGE) * STAGE_BYTES;
        uint32_t stB = stA + 16384;

#pragma unroll
        for (int kk = 0; kk < 4; kk++) {
            uint32_t ko = (uint32_t)(kk * 32 + hh * 16);
            uint32_t ah[4][4], bh[8][2];
#pragma unroll
            for (int mt = 0; mt < 4; mt++) {
                uint32_t ad = stA + cA[mt] + (ko ^ swA[mt]);
                LDSM4(ah[mt][0], ah[mt][1], ah[mt][2], ah[mt][3], ad);
            }
#pragma unroll
            for (int q = 0; q < 4; q++) {
                uint32_t ad = stB + cB[q] + (ko ^ swB[q]);
                uint32_t r0, r1, r2, r3;
                LDSM4(r0, r1, r2, r3, ad);
                bh[2 * q][0] = r0; bh[2 * q + 1][0] = r1;
                bh[2 * q][1] = r2; bh[2 * q + 1][1] = r3;
            }
#pragma unroll
            for (int mt = 0; mt < 4; mt++)
#pragma unroll
                for (int nt = 0; nt < 8; nt++)
                    MMA16816(acc[mt][nt], ah[mt], bh[nt]);
        }
    }

    // ---- epilogue: bias + GLU -> d_U ----
    int g = lane >> 2, t = lane & 3;
    const float* bias = (bn >= 2) ? mcb : ccb;
    int ucb = ((bn >> 1) << 7);               // d_U column base (branch)
#pragma unroll
    for (int mt = 0; mt < 4; mt++) {
        int r0 = m0 + wm * 64 + mt * 16 + g;
#pragma unroll
        for (int nt = 0; nt < 8; nt++) {
            int p = ((bn & 1) << 6) + wn * 32 + nt * 4 + t;
            float ba = __ldg(bias + p);
            float bg = __ldg(bias + 128 + p);
            int uc = ucb + p;
            float a0 = acc[mt][nt][0] + ba;
            float g0 = acc[mt][nt][1] + bg;
            d_U[(size_t)r0 * 256 + uc] = a0 / (1.f + __expf(-g0));
            float a1 = acc[mt][nt][2] + ba;
            float g1 = acc[mt][nt][3] + bg;
            d_U[(size_t)(r0 + 8) * 256 + uc] = a1 / (1.f + __expf(-g1));
        }
    }
}

// ============================================================
// K2a: ctx share + leaky + per-chunk channel max -> d_gpart.
// ============================================================
__global__ __launch_bounds__(256) void share_ctx(const float* __restrict__ csb) {
    __shared__ float u[32][132];
    __shared__ float redmax[8][CC];
    int tid = threadIdx.x;
    int blk = blockIdx.x;
    int b = blk / GCHUNKS, ch = blk % GCHUNKS;
    int row0 = b * TOUT + ch * 31;

    for (int i = tid; i < 32 * 32; i += 256) {
        int r = i >> 5, q4 = (i & 31) * 4;
        float4 v = *(const float4*)(d_U + (size_t)(row0 + r) * 256 + q4);
        u[r][q4] = v.x; u[r][q4 + 1] = v.y; u[r][q4 + 2] = v.z; u[r][q4 + 3] = v.w;
    }
    __syncthreads();

    int ty = tid >> 5;
    int tx = tid & 31;
    int ol = tx * 4;
    const float* wt = d_WsT[0];

    float acc[4][4];
#pragma unroll
    for (int i = 0; i < 4; i++)
#pragma unroll
        for (int j = 0; j < 4; j++) acc[i][j] = 0.f;

    for (int c = 0; c < CC; c++) {
        float4 w0 = __ldg((const float4*)(wt + c * CC + ol));
        float wv[4] = {w0.x, w0.y, w0.z, w0.w};
        float uv[4];
#pragma unroll
        for (int i = 0; i < 4; i++) uv[i] = u[ty * 4 + i][c];
#pragma unroll
        for (int i = 0; i < 4; i++)
#pragma unroll
            for (int j = 0; j < 4; j++) acc[i][j] += uv[i] * wv[j];
    }

    float b4[4];
#pragma unroll
    for (int j = 0; j < 4; j++) b4[j] = __ldg(csb + ol + j);

    float m4[4] = {-INFINITY, -INFINITY, -INFINITY, -INFINITY};
#pragma unroll
    for (int i = 0; i < 4; i++) {
        int lr = ty * 4 + i;
        if (lr < 31) {
#pragma unroll
            for (int j = 0; j < 4; j++) {
                float v = acc[i][j] + b4[j];
                v = (v >= 0.f) ? v : 0.01f * v;
                m4[j] = fmaxf(m4[j], v);
            }
        }
    }
#pragma unroll
    for (int j = 0; j < 4; j++) redmax[ty][ol + j] = m4[j];
    __syncthreads();
    if (tid < CC) {
        float m = redmax[0][tid];
#pragma unroll
        for (int i = 1; i < 8; i++) m = fmaxf(m, redmax[i][tid]);
        d_gpart[(size_t)blk * CC + tid] = m;
    }
}

// ============================================================
// K3: fused gct reduce + q projection, SMEM-staged weights.
//     grid(BB), 128 threads.  w staged coalesced into padded
//     SMEM (stride 129 -> conflict-free row reads).
// ============================================================
__global__ void gct_q(const float* __restrict__ w, const float* __restrict__ bq) {
    extern __shared__ float sm[];          // ws[128*129] + gs[128]
    float* ws = sm;
    float* gs = sm + 128 * 129;
    int b = blockIdx.x, c = threadIdx.x;

    // stage w coalesced: 4096 float4 by 128 threads
    for (int i = c; i < 4096; i += 128) {
        float4 v = __ldg((const float4*)w + i);
        int o = i >> 5;              // row (32 float4 per row)
        int q4 = (i & 31) * 4;
        float* dst = ws + o * 129 + q4;
        dst[0] = v.x; dst[1] = v.y; dst[2] = v.z; dst[3] = v.w;
    }

    // gct reduce over 63 chunks
    float m = -INFINITY;
    for (int i = 0; i < GCHUNKS; i++)
        m = fmaxf(m, d_gpart[((size_t)b * GCHUNKS + i) * CC + c]);
    gs[c] = m;
    __syncthreads();

    float s = __ldg(bq + c);
    const float* wr = ws + c * 129;
#pragma unroll 8
    for (int k = 0; k < CC; k++) s += gs[k] * wr[k];
    d_q[b * CC + c] = tanhf(s);
}

// ============================================================
// K2b: main share + leaky (SMEM) + fused gate + per-chunk max.
// ============================================================
__global__ __launch_bounds__(256) void share_main_gate(const float* __restrict__ msb) {
    __shared__ float u[32][132];
    __shared__ float hs[32][CC];
    __shared__ float qs[CC];
    __shared__ float wm[8][CC];
    int tid = threadIdx.x;
    int blk = blockIdx.x;
    int b = blk / GCHUNKS, ch = blk % GCHUNKS;
    int row0 = b * TOUT + ch * 31;

    if (tid < CC) qs[tid] = d_q[b * CC + tid];
    for (int i = tid; i < 32 * 32; i += 256) {
        int r = i >> 5, q4 = (i & 31) * 4;
        float4 v = *(const float4*)(d_U + (size_t)(row0 + r) * 256 + 128 + q4);
        u[r][q4] = v.x; u[r][q4 + 1] = v.y; u[r][q4 + 2] = v.z; u[r][q4 + 3] = v.w;
    }
    __syncthreads();

    int ty = tid >> 5;
    int tx = tid & 31;
    int ol = tx * 4;
    const float* wt = d_WsT[1];

    float acc[4][4];
#pragma unroll
    for (int i = 0; i < 4; i++)
#pragma unroll
        for (int j = 0; j < 4; j++) acc[i][j] = 0.f;

    for (int c = 0; c < CC; c++) {
        float4 w0 = __ldg((const float4*)(wt + c * CC + ol));
        float wv[4] = {w0.x, w0.y, w0.z, w0.w};
        float uv[4];
#pragma unroll
        for (int i = 0; i < 4; i++) uv[i] = u[ty * 4 + i][c];
#pragma unroll
        for (int i = 0; i < 4; i++)
#pragma unroll
            for (int j = 0; j < 4; j++) acc[i][j] += uv[i] * wv[j];
    }

    float b4[4];
#pragma unroll
    for (int j = 0; j < 4; j++) b4[j] = __ldg(msb + ol + j);
#pragma unroll
    for (int i = 0; i < 4; i++) {
        int lr = ty * 4 + i;
#pragma unroll
        for (int j = 0; j < 4; j++) {
            float v = acc[i][j] + b4[j];
            hs[lr][ol + j] = (v >= 0.f) ? v : 0.01f * v;
        }
    }
    __syncthreads();

    int w = tid >> 5, lane = tid & 31;
    float vmax[4] = {-INFINITY, -INFINITY, -INFINITY, -INFINITY};
#pragma unroll
    for (int rep = 0; rep < 4; rep++) {
        int lr = rep * 8 + w;
        if (lr < 31) {
            float hv[4];
            float dot = 0.f;
#pragma unroll
            for (int j = 0; j < 4; j++) {
                hv[j] = hs[lr][lane + 32 * j];
                dot += hv[j] * qs[lane + 32 * j];
            }
#pragma unroll
            for (int off = 16; off; off >>= 1)
                dot += __shfl_xor_sync(0xffffffff, dot, off);
            float gate = 1.f / (1.f + __expf(-dot));
#pragma unroll
            for (int j = 0; j < 4; j++)
                vmax[j] = fmaxf(vmax[j], hv[j] * gate);
        }
    }
#pragma unroll
    for (int j = 0; j < 4; j++) wm[w][lane + 32 * j] = vmax[j];
    __syncthreads();
    if (tid < CC) {
        float m = wm[0][tid];
#pragma unroll
        for (int i = 1; i < 8; i++) m = fmaxf(m, wm[i][tid]);
        d_part[(size_t)blk * CC + tid] = m;
    }
}

// K6: final reduce -> out (B, C)
__global__ void final_max(float* __restrict__ out) {
    int b = blockIdx.x, c = threadIdx.x;
    float m = -INFINITY;
    for (int i = 0; i < GCHUNKS; i++)
        m = fmaxf(m, d_part[((size_t)b * GCHUNKS + i) * CC + c]);
    out[b * CC + c] = m;
}

// ============================================================
extern "C" void kernel_launch(void* const* d_in, const int* in_sizes, int n_in,
                              void* d_out, int out_size) {
    const float* x   = (const float*)d_in[0];
    const float* ccw = (const float*)d_in[1];
    const float* ccb = (const float*)d_in[2];
    const float* csw = (const float*)d_in[3];
    const float* csb = (const float*)d_in[4];
    const float* mcw = (const float*)d_in[5];
    const float* mcb = (const float*)d_in[6];
    const float* msw = (const float*)d_in[7];
    const float* msb = (const float*)d_in[8];
    const float* gpw = (const float*)d_in[9];
    const float* gpb = (const float*)d_in[10];
    float* out = (float*)d_out;

    static int smem_set = 0;
    if (!smem_set) {
        cudaFuncSetAttribute(gemm_tc, cudaFuncAttributeMaxDynamicSharedMemorySize, SMEM_DYN);
        cudaFuncSetAttribute(gct_q, cudaFuncAttributeMaxDynamicSharedMemorySize, GCTQ_SMEM);
        smem_set = 1;
    }

    prep_fp16A<<<dim3(2, MP), 256>>>(x);
    prep_fp16B<<<(NCOLS * KDIM + 255) / 256, 256>>>(ccw, mcw);
    prep_wst<<<(CC * CC + 255) / 256, 256>>>(csw, msw);

    gemm_tc<<<dim3(4, MP / BM), 128, SMEM_DYN>>>(ccb, mcb);

    share_ctx<<<BB * GCHUNKS, 256>>>(csb);
    gct_q<<<BB, CC, GCTQ_SMEM>>>(gpw, gpb);
    share_main_gate<<<BB * GCHUNKS, 256>>>(msb);
    final_max<<<BB, CC>>>(out);
}

// round 15
// speedup vs baseline: 1.4274x; 1.4274x over previous
#include <cuda_runtime.h>
#include <cuda_fp16.h>
#include <math.h>
#include <stdint.h>

// ---------------- problem constants ----------------
#define BB    4
#define TT    1000000
#define EE    8
#define CC    128
#define TOUT  1953
#define MROWS (BB * TOUT)          // 7812
#define MP    7936                 // padded M = 62*128
#define NCOLS 512
#define KDIM  4096
#define GCHUNKS 63                 // 31-row chunks per batch (63*31 = 1953)

// ---------------- GEMM tiling ----------------
#define BM 128
#define BN 128
#define BKC 64                     // K elems per stage
#define NKC (KDIM / BKC)           // 64 chunks
#define STAGE_BYTES 32768          // A 16K + B 16K (fp16)
#define NSTAGE 3
#define SMEM_DYN (NSTAGE * STAGE_BYTES)   // 98304

// gct_q smem: 128 x 129 floats (padded) + 128 gs
#define GCTQ_SMEM ((128 * 129 + 128) * 4)

// ---------------- scratch ----------------
__device__ __half d_Ah[(size_t)MP * KDIM];
__device__ __half d_Bh[(size_t)NCOLS * KDIM];   // column-interleaved (a,gate pairs)
__device__ float d_U[(size_t)MP * 256];   // GLU out [row][ctx 0..127 | main 0..127]
__device__ float d_WsT[2][CC * CC];
__device__ float d_gpart[BB * GCHUNKS * CC];
__device__ float d_q[BB * CC];
__device__ float d_part[BB * GCHUNKS * CC];

// ---------------- PTX helpers ----------------
__device__ __forceinline__ uint32_t smem_u32(const void* p) {
    uint32_t a;
    asm("{ .reg .u64 t; cvta.to.shared.u64 t, %1; cvt.u32.u64 %0, t; }" : "=r"(a) : "l"(p));
    return a;
}
#define CP16(dst, src) asm volatile("cp.async.cg.shared.global [%0], [%1], 16;" :: "r"(dst), "l"(src) : "memory")
#define CP_COMMIT()    asm volatile("cp.async.commit_group;" ::: "memory")
#define CP_WAIT1()     asm volatile("cp.async.wait_group 1;" ::: "memory")

#define LDSM4(r0, r1, r2, r3, addr)                                         \
    asm volatile("ldmatrix.sync.aligned.m8n8.x4.shared.b16 {%0,%1,%2,%3}, [%4];" \
        : "=r"(r0), "=r"(r1), "=r"(r2), "=r"(r3) : "r"(addr))

#define MMA16816(d, a, b)                                                   \
    asm volatile("mma.sync.aligned.m16n8k16.row.col.f32.f16.f16.f32 "       \
        "{%0,%1,%2,%3}, {%4,%5,%6,%7}, {%8,%9}, {%0,%1,%2,%3};"             \
        : "+f"((d)[0]), "+f"((d)[1]), "+f"((d)[2]), "+f"((d)[3])            \
        : "r"((a)[0]), "r"((a)[1]), "r"((a)[2]), "r"((a)[3]),               \
          "r"((b)[0]), "r"((b)[1]))

// swizzled byte offset within a 128B-row tile: row r, 16B-column c16
__device__ __forceinline__ uint32_t tile_off(int r, int c16) {
    return (uint32_t)(r * 128 + ((c16 * 16) ^ ((r & 7) << 4)));
}

// ============================================================
// Prep: convert x windows to fp16 (rows padded to MP)
// ============================================================
__global__ void prep_fp16A(const float* __restrict__ x) {
    int r = blockIdx.y;
    int k = blockIdx.x * 2048 + threadIdx.x * 8;
    size_t o = (size_t)r * KDIM + k;
    if (r >= MROWS) {
        *(uint4*)(d_Ah + o) = make_uint4(0, 0, 0, 0);
        return;
    }
    int b = r / TOUT, t = r % TOUT;
    const float* src = x + (size_t)b * TT * EE + (size_t)t * KDIM + k;
    float4 v0 = *(const float4*)(src);
    float4 v1 = *(const float4*)(src + 4);
    __half2* ph = (__half2*)(d_Ah + o);
    ph[0] = __floats2half2_rn(v0.x, v0.y);
    ph[1] = __floats2half2_rn(v0.z, v0.w);
    ph[2] = __floats2half2_rn(v1.x, v1.y);
    ph[3] = __floats2half2_rn(v1.z, v1.w);
}

// B weights -> fp16 column-interleaved, and share weights -> WsT.
// blocks [0, 8192): B.  blocks [8192, 8256): WsT.
// B interleave: n_new = branch*256 + pair*2 + half
// (pair = GLU channel, half 0 = "a", 1 = "gate"); kk = k*8 + e
__global__ void prep_w(const float* __restrict__ cw, const float* __restrict__ mw,
                       const float* __restrict__ cs, const float* __restrict__ ms) {
    int bid = blockIdx.x;
    if (bid < 8192) {
        int idx = bid * 256 + threadIdx.x;        // < NCOLS*KDIM = 2M
        int n = idx >> 12, kk = idx & 4095;
        int branch = n >> 8;
        int within = n & 255;
        int pair = within >> 1, half = within & 1;
        int oc = half * 128 + pair;               // original out-channel within branch
        int e = kk & 7, k = kk >> 3;
        const float* w = branch ? mw : cw;
        d_Bh[idx] = __float2half_rn(w[(size_t)oc * KDIM + e * 512 + k]);
    } else {
        int idx = (bid - 8192) * 256 + threadIdx.x;
        if (idx < CC * CC) {
            int o = idx / CC, c = idx % CC;
            d_WsT[0][c * CC + o] = cs[o * CC + c];
            d_WsT[1][c * CC + o] = ms[o * CC + c];
        }
    }
}

// ============================================================
// K1: fp16 HMMA GEMM + fused bias/GLU -> d_U   (R10 verbatim)
//     grid (4, 62); 128 threads = 4 warps (2m x 2n),
//     warp tile 64x64, 3-stage cp.async, 2 CTAs/SM.
// ============================================================
__global__ __launch_bounds__(128, 2) void gemm_tc(const float* __restrict__ ccb,
                                                  const float* __restrict__ mcb) {
    extern __shared__ char smem[];
    uint32_t sbase = smem_u32(smem);
    int tid = threadIdx.x;
    int lane = tid & 31, wid = tid >> 5;
    int wm = wid & 1, wn = wid >> 1;          // 2 x 2 warp grid
    int bn = blockIdx.x, bm = blockIdx.y;
    int m0 = bm * BM, n0 = bn * BN;

    int l15 = lane & 15, hh = lane >> 4;
    uint32_t cA[4], swA[4], cB[4], swB[4];
#pragma unroll
    for (int mt = 0; mt < 4; mt++) {
        int r = wm * 64 + mt * 16 + l15;
        cA[mt] = (uint32_t)(r * 128);
        swA[mt] = (uint32_t)((r & 7) << 4);
    }
#pragma unroll
    for (int q = 0; q < 4; q++) {
        int r = wn * 64 + q * 16 + l15;
        cB[q] = (uint32_t)(r * 128);
        swB[q] = (uint32_t)((r & 7) << 4);
    }

    float acc[4][8][4];
#pragma unroll
    for (int mt = 0; mt < 4; mt++)
#pragma unroll
        for (int nt = 0; nt < 8; nt++)
#pragma unroll
            for (int i = 0; i < 4; i++) acc[mt][nt][i] = 0.f;

    // ---- prologue: load stages 0,1 (8 A + 8 B cp.async per thread) ----
#pragma unroll
    for (int s = 0; s < 2; s++) {
        uint32_t stg = sbase + s * STAGE_BYTES;
        size_t koff = (size_t)s * BKC;
#pragma unroll
        for (int i = 0; i < 8; i++) {
            int idx = tid + i * 128;
            int row = idx >> 3, c16 = idx & 7;
            uint32_t dst = tile_off(row, c16);
            size_t ga = (size_t)(m0 + row) * KDIM + koff + c16 * 8;
            size_t gb = (size_t)(n0 + row) * KDIM + koff + c16 * 8;
            CP16(stg + dst,         d_Ah + ga);
            CP16(stg + 16384 + dst, d_Bh + gb);
        }
        CP_COMMIT();
    }

    // ---- main loop ----
    for (int c = 0; c < NKC; c++) {
        CP_WAIT1();
        __syncthreads();

        if (c + 2 < NKC) {
            uint32_t stg = sbase + ((c + 2) % NSTAGE) * STAGE_BYTES;
            size_t koff = (size_t)(c + 2) * BKC;
#pragma unroll
            for (int i = 0; i < 8; i++) {
                int idx = tid + i * 128;
                int row = idx >> 3, c16 = idx & 7;
                uint32_t dst = tile_off(row, c16);
                size_t ga = (size_t)(m0 + row) * KDIM + koff + c16 * 8;
                size_t gb = (size_t)(n0 + row) * KDIM + koff + c16 * 8;
                CP16(stg + dst,         d_Ah + ga);
                CP16(stg + 16384 + dst, d_Bh + gb);
            }
        }
        CP_COMMIT();

        uint32_t stA = sbase + (c % NSTAGE) * STAGE_BYTES;
        uint32_t stB = stA + 16384;

#pragma unroll
        for (int kk = 0; kk < 4; kk++) {
            uint32_t ko = (uint32_t)(kk * 32 + hh * 16);
            uint32_t ah[4][4], bh[8][2];
#pragma unroll
            for (int mt = 0; mt < 4; mt++) {
                uint32_t ad = stA + cA[mt] + (ko ^ swA[mt]);
                LDSM4(ah[mt][0], ah[mt][1], ah[mt][2], ah[mt][3], ad);
            }
#pragma unroll
            for (int q = 0; q < 4; q++) {
                uint32_t ad = stB + cB[q] + (ko ^ swB[q]);
                uint32_t r0, r1, r2, r3;
                LDSM4(r0, r1, r2, r3, ad);
                bh[2 * q][0] = r0; bh[2 * q + 1][0] = r1;
                bh[2 * q][1] = r2; bh[2 * q + 1][1] = r3;
            }
#pragma unroll
            for (int mt = 0; mt < 4; mt++)
#pragma unroll
                for (int nt = 0; nt < 8; nt++)
                    MMA16816(acc[mt][nt], ah[mt], bh[nt]);
        }
    }

    // ---- epilogue: bias + GLU -> d_U ----
    int g = lane >> 2, t = lane & 3;
    const float* bias = (bn >= 2) ? mcb : ccb;
    int ucb = ((bn >> 1) << 7);               // d_U column base (branch)
#pragma unroll
    for (int mt = 0; mt < 4; mt++) {
        int r0 = m0 + wm * 64 + mt * 16 + g;
#pragma unroll
        for (int nt = 0; nt < 8; nt++) {
            int p = ((bn & 1) << 6) + wn * 32 + nt * 4 + t;
            float ba = __ldg(bias + p);
            float bg = __ldg(bias + 128 + p);
            int uc = ucb + p;
            float a0 = acc[mt][nt][0] + ba;
            float g0 = acc[mt][nt][1] + bg;
            d_U[(size_t)r0 * 256 + uc] = a0 / (1.f + __expf(-g0));
            float a1 = acc[mt][nt][2] + ba;
            float g1 = acc[mt][nt][3] + bg;
            d_U[(size_t)(r0 + 8) * 256 + uc] = a1 / (1.f + __expf(-g1));
        }
    }
}

// ============================================================
// K2a: ctx share + leaky + per-chunk channel max -> d_gpart.
// ============================================================
__global__ __launch_bounds__(256) void share_ctx(const float* __restrict__ csb) {
    __shared__ float u[32][132];
    __shared__ float redmax[8][CC];
    int tid = threadIdx.x;
    int blk = blockIdx.x;
    int b = blk / GCHUNKS, ch = blk % GCHUNKS;
    int row0 = b * TOUT + ch * 31;

    for (int i = tid; i < 32 * 32; i += 256) {
        int r = i >> 5, q4 = (i & 31) * 4;
        float4 v = *(const float4*)(d_U + (size_t)(row0 + r) * 256 + q4);
        u[r][q4] = v.x; u[r][q4 + 1] = v.y; u[r][q4 + 2] = v.z; u[r][q4 + 3] = v.w;
    }
    __syncthreads();

    int ty = tid >> 5;
    int tx = tid & 31;
    int ol = tx * 4;
    const float* wt = d_WsT[0];

    float acc[4][4];
#pragma unroll
    for (int i = 0; i < 4; i++)
#pragma unroll
        for (int j = 0; j < 4; j++) acc[i][j] = 0.f;

    for (int c = 0; c < CC; c++) {
        float4 w0 = __ldg((const float4*)(wt + c * CC + ol));
        float wv[4] = {w0.x, w0.y, w0.z, w0.w};
        float uv[4];
#pragma unroll
        for (int i = 0; i < 4; i++) uv[i] = u[ty * 4 + i][c];
#pragma unroll
        for (int i = 0; i < 4; i++)
#pragma unroll
            for (int j = 0; j < 4; j++) acc[i][j] += uv[i] * wv[j];
    }

    float b4[4];
#pragma unroll
    for (int j = 0; j < 4; j++) b4[j] = __ldg(csb + ol + j);

    float m4[4] = {-INFINITY, -INFINITY, -INFINITY, -INFINITY};
#pragma unroll
    for (int i = 0; i < 4; i++) {
        int lr = ty * 4 + i;
        if (lr < 31) {
#pragma unroll
            for (int j = 0; j < 4; j++) {
                float v = acc[i][j] + b4[j];
                v = (v >= 0.f) ? v : 0.01f * v;
                m4[j] = fmaxf(m4[j], v);
            }
        }
    }
#pragma unroll
    for (int j = 0; j < 4; j++) redmax[ty][ol + j] = m4[j];
    __syncthreads();
    if (tid < CC) {
        float m = redmax[0][tid];
#pragma unroll
        for (int i = 1; i < 8; i++) m = fmaxf(m, redmax[i][tid]);
        d_gpart[(size_t)blk * CC + tid] = m;
    }
}

// ============================================================
// K3: fused gct reduce + q projection, SMEM-staged weights.
//     grid(BB), 128 threads; w staged coalesced, stride-129 pad.
// ============================================================
__global__ void gct_q(const float* __restrict__ w, const float* __restrict__ bq) {
    extern __shared__ float sm[];          // ws[128*129] + gs[128]
    float* ws = sm;
    float* gs = sm + 128 * 129;
    int b = blockIdx.x, c = threadIdx.x;

    for (int i = c; i < 4096; i += 128) {
        float4 v = __ldg((const float4*)w + i);
        int o = i >> 5;
        int q4 = (i & 31) * 4;
        float* dst = ws + o * 129 + q4;
        dst[0] = v.x; dst[1] = v.y; dst[2] = v.z; dst[3] = v.w;
    }

    float m = -INFINITY;
    for (int i = 0; i < GCHUNKS; i++)
        m = fmaxf(m, d_gpart[((size_t)b * GCHUNKS + i) * CC + c]);
    gs[c] = m;
    __syncthreads();

    float s = __ldg(bq + c);
    const float* wr = ws + c * 129;
#pragma unroll 8
    for (int k = 0; k < CC; k++) s += gs[k] * wr[k];
    d_q[b * CC + c] = tanhf(s);
}

// ============================================================
// K2b: main share + leaky (SMEM) + fused gate + per-chunk max.
// ============================================================
__global__ __launch_bounds__(256) void share_main_gate(const float* __restrict__ msb) {
    __shared__ float u[32][132];
    __shared__ float hs[32][CC];
    __shared__ float qs[CC];
    __shared__ float wm[8][CC];
    int tid = threadIdx.x;
    int blk = blockIdx.x;
    int b = blk / GCHUNKS, ch = blk % GCHUNKS;
    int row0 = b * TOUT + ch * 31;

    if (tid < CC) qs[tid] = d_q[b * CC + tid];
    for (int i = tid; i < 32 * 32; i += 256) {
        int r = i >> 5, q4 = (i & 31) * 4;
        float4 v = *(const float4*)(d_U + (size_t)(row0 + r) * 256 + 128 + q4);
        u[r][q4] = v.x; u[r][q4 + 1] = v.y; u[r][q4 + 2] = v.z; u[r][q4 + 3] = v.w;
    }
    __syncthreads();

    int ty = tid >> 5;
    int tx = tid & 31;
    int ol = tx * 4;
    const float* wt = d_WsT[1];

    float acc[4][4];
#pragma unroll
    for (int i = 0; i < 4; i++)
#pragma unroll
        for (int j = 0; j < 4; j++) acc[i][j] = 0.f;

    for (int c = 0; c < CC; c++) {
        float4 w0 = __ldg((const float4*)(wt + c * CC + ol));
        float wv[4] = {w0.x, w0.y, w0.z, w0.w};
        float uv[4];
#pragma unroll
        for (int i = 0; i < 4; i++) uv[i] = u[ty * 4 + i][c];
#pragma unroll
        for (int i = 0; i < 4; i++)
#pragma unroll
            for (int j = 0; j < 4; j++) acc[i][j] += uv[i] * wv[j];
    }

    float b4[4];
#pragma unroll
    for (int j = 0; j < 4; j++) b4[j] = __ldg(msb + ol + j);
#pragma unroll
    for (int i = 0; i < 4; i++) {
        int lr = ty * 4 + i;
#pragma unroll
        for (int j = 0; j < 4; j++) {
            float v = acc[i][j] + b4[j];
            hs[lr][ol + j] = (v >= 0.f) ? v : 0.01f * v;
        }
    }
    __syncthreads();

    int w = tid >> 5, lane = tid & 31;
    float vmax[4] = {-INFINITY, -INFINITY, -INFINITY, -INFINITY};
#pragma unroll
    for (int rep = 0; rep < 4; rep++) {
        int lr = rep * 8 + w;
        if (lr < 31) {
            float hv[4];
            float dot = 0.f;
#pragma unroll
            for (int j = 0; j < 4; j++) {
                hv[j] = hs[lr][lane + 32 * j];
                dot += hv[j] * qs[lane + 32 * j];
            }
#pragma unroll
            for (int off = 16; off; off >>= 1)
                dot += __shfl_xor_sync(0xffffffff, dot, off);
            float gate = 1.f / (1.f + __expf(-dot));
#pragma unroll
            for (int j = 0; j < 4; j++)
                vmax[j] = fmaxf(vmax[j], hv[j] * gate);
        }
    }
#pragma unroll
    for (int j = 0; j < 4; j++) wm[w][lane + 32 * j] = vmax[j];
    __syncthreads();
    if (tid < CC) {
        float m = wm[0][tid];
#pragma unroll
        for (int i = 1; i < 8; i++) m = fmaxf(m, wm[i][tid]);
        d_part[(size_t)blk * CC + tid] = m;
    }
}

// K6: final reduce -> out (B, C)
__global__ void final_max(float* __restrict__ out) {
    int b = blockIdx.x, c = threadIdx.x;
    float m = -INFINITY;
    for (int i = 0; i < GCHUNKS; i++)
        m = fmaxf(m, d_part[((size_t)b * GCHUNKS + i) * CC + c]);
    out[b * CC + c] = m;
}

// ============================================================
extern "C" void kernel_launch(void* const* d_in, const int* in_sizes, int n_in,
                              void* d_out, int out_size) {
    const float* x   = (const float*)d_in[0];
    const float* ccw = (const float*)d_in[1];
    const float* ccb = (const float*)d_in[2];
    const float* csw = (const float*)d_in[3];
    const float* csb = (const float*)d_in[4];
    const float* mcw = (const float*)d_in[5];
    const float* mcb = (const float*)d_in[6];
    const float* msw = (const float*)d_in[7];
    const float* msb = (const float*)d_in[8];
    const float* gpw = (const float*)d_in[9];
    const float* gpb = (const float*)d_in[10];
    float* out = (float*)d_out;

    cudaFuncSetAttribute(gemm_tc, cudaFuncAttributeMaxDynamicSharedMemorySize, SMEM_DYN);
    cudaFuncSetAttribute(gct_q, cudaFuncAttributeMaxDynamicSharedMemorySize, GCTQ_SMEM);

    prep_fp16A<<<dim3(2, MP), 256>>>(x);
    prep_w<<<8192 + 64, 256>>>(ccw, mcw, csw, msw);

    gemm_tc<<<dim3(4, MP / BM), 128, SMEM_DYN>>>(ccb, mcb);

    share_ctx<<<BB * GCHUNKS, 256>>>(csb);
    gct_q<<<BB, CC, GCTQ_SMEM>>>(gpw, gpb);
    share_main_gate<<<BB * GCHUNKS, 256>>>(msb);
    final_max<<<BB, CC>>>(out);
}